// round 2
// baseline (speedup 1.0000x reference)
#include <cuda_runtime.h>
#include <cuda_bf16.h>
#include <math.h>

// Problem constants
#define BATCH 256
#define TOBS  80
#define TFUT  80
#define TTOT  160
#define HID   2048
#define HID4  8192
#define BH    (BATCH * HID)

// GEMM tile config
#define BM 128
#define BN 128   // 32 hidden units * 4 gates (interleaved: col n -> jl = n>>2, gate = n&3)
#define BK 16
#define NTHREADS 256

// Persistent state buffers (ping-pong)
__device__ float g_h[2 * BH];
__device__ float g_c[2 * BH];
__device__ float g_xfb[BATCH];

__device__ __forceinline__ float sigf(float v) {
    return 1.0f / (1.0f + expf(-v));
}

// ---- packed f32x2 helpers ----
__device__ __forceinline__ void fma2(unsigned long long& acc, unsigned long long a, unsigned long long b) {
    asm("fma.rn.f32x2 %0, %1, %2, %0;" : "+l"(acc) : "l"(a), "l"(b));
}
__device__ __forceinline__ unsigned long long pack2(float lo, float hi) {
    unsigned long long d;
    asm("mov.b64 %0, {%1, %2};" : "=l"(d) : "f"(lo), "f"(hi));
    return d;
}
__device__ __forceinline__ void unpack2(unsigned long long v, float& lo, float& hi) {
    asm("mov.b64 {%0, %1}, %2;" : "=f"(lo), "=f"(hi) : "l"(v));
}

__global__ void init_zero_kernel(float* h0, float* c0, int n) {
    int i = blockIdx.x * blockDim.x + threadIdx.x;
    if (i < n) { h0[i] = 0.0f; c0[i] = 0.0f; }
}

// Fused: gates = h_prev @ W_hh^T + x*W_ih + b ; then LSTM cell update -> h_next, c_next
// Block: (bx in 0..1) batch tile of 128, (by in 0..63) hidden tile of 32 units.
// Column n in 0..127: jl = n>>2, gate g = n&3 ; gate row = g*HID + j0 + jl.
__global__ void __launch_bounds__(NTHREADS, 1)
lstm_step_kernel(const float* __restrict__ h_prev,
                 const float* __restrict__ c_prev,
                 float* __restrict__ h_next,
                 float* __restrict__ c_next,
                 const float* __restrict__ W_hh,   // [8192, 2048] row-major
                 const float* __restrict__ W_ih,   // [8192]
                 const float* __restrict__ b_ih,   // [8192]
                 const float* __restrict__ b_hh,   // [8192]
                 const float* __restrict__ xvec,   // x input: xvec[b * xstride]
                 int xstride)
{
    __shared__ __align__(16) float As[BK][BM];
    __shared__ __align__(16) float Bs[BK][BN];

    const int tid = threadIdx.x;
    const int tx = tid & 15;       // 0..15 -> cols tx*8..tx*8+7
    const int ty = tid >> 4;       // 0..15 -> rows ty*8..ty*8+7
    const int bm0 = blockIdx.x * BM;
    const int j0  = blockIdx.y * 32;

    // Precompute global source rows for the two loads each thread does per tile.
    // f = tid + 256*r ; row/n = f>>2 ; c4 = (f&3)*4
    const float* aptr[2];
    const float* bptr[2];
    #pragma unroll
    for (int r = 0; r < 2; ++r) {
        int f = tid + 256 * r;
        int row = f >> 2;
        int c4  = (f & 3) * 4;
        aptr[r] = h_prev + (size_t)(bm0 + row) * HID + c4;
        int jl = row >> 2;
        int g  = row & 3;
        int grow = g * HID + j0 + jl;
        bptr[r] = W_hh + (size_t)grow * HID + c4;
    }

    unsigned long long acc[32];   // acc[m*4+p] : m=0..7 rows, p=0..3 col-pairs
    #pragma unroll
    for (int i = 0; i < 32; ++i) acc[i] = 0ULL;

    for (int kt = 0; kt < HID; kt += BK) {
        // Load tiles
        #pragma unroll
        for (int r = 0; r < 2; ++r) {
            int f = tid + 256 * r;
            int row = f >> 2;
            int c4  = (f & 3) * 4;
            float4 va = *(const float4*)(aptr[r] + kt);
            As[c4 + 0][row] = va.x; As[c4 + 1][row] = va.y;
            As[c4 + 2][row] = va.z; As[c4 + 3][row] = va.w;
            float4 vb = *(const float4*)(bptr[r] + kt);
            Bs[c4 + 0][row] = vb.x; Bs[c4 + 1][row] = vb.y;
            Bs[c4 + 2][row] = vb.z; Bs[c4 + 3][row] = vb.w;
        }
        __syncthreads();

        #pragma unroll
        for (int k = 0; k < BK; ++k) {
            float4 a0 = *(const float4*)&As[k][ty * 8];
            float4 a1 = *(const float4*)&As[k][ty * 8 + 4];
            float4 b0 = *(const float4*)&Bs[k][tx * 8];
            float4 b1 = *(const float4*)&Bs[k][tx * 8 + 4];

            unsigned long long B2[4];
            B2[0] = pack2(b0.x, b0.y); B2[1] = pack2(b0.z, b0.w);
            B2[2] = pack2(b1.x, b1.y); B2[3] = pack2(b1.z, b1.w);

            unsigned long long A2[8];
            A2[0] = pack2(a0.x, a0.x); A2[1] = pack2(a0.y, a0.y);
            A2[2] = pack2(a0.z, a0.z); A2[3] = pack2(a0.w, a0.w);
            A2[4] = pack2(a1.x, a1.x); A2[5] = pack2(a1.y, a1.y);
            A2[6] = pack2(a1.z, a1.z); A2[7] = pack2(a1.w, a1.w);

            #pragma unroll
            for (int m = 0; m < 8; ++m) {
                #pragma unroll
                for (int p = 0; p < 4; ++p) {
                    fma2(acc[m * 4 + p], A2[m], B2[p]);
                }
            }
        }
        __syncthreads();
    }

    // Epilogue: columns tx*8+idx -> q = idx>>2 in {0,1}, gate = idx&3 (i,f,g,o)
    //   pair p=2q   : (gi, gf)
    //   pair p=2q+1 : (gg, go)
    // hidden unit j = j0 + 2*tx + q
    const int bbase = bm0 + ty * 8;

    #pragma unroll
    for (int q = 0; q < 2; ++q) {
        const int j = j0 + tx * 2 + q;
        const float bi = b_ih[j]           + b_hh[j];
        const float bf = b_ih[HID + j]     + b_hh[HID + j];
        const float bg = b_ih[2 * HID + j] + b_hh[2 * HID + j];
        const float bo = b_ih[3 * HID + j] + b_hh[3 * HID + j];
        const float wi = W_ih[j];
        const float wf = W_ih[HID + j];
        const float wg = W_ih[2 * HID + j];
        const float wo = W_ih[3 * HID + j];

        #pragma unroll
        for (int m = 0; m < 8; ++m) {
            const int b = bbase + m;
            const float xin = xvec[(size_t)b * xstride];
            float gi, gf, gg, go;
            unpack2(acc[m * 4 + 2 * q],     gi, gf);
            unpack2(acc[m * 4 + 2 * q + 1], gg, go);
            gi += bi + xin * wi;
            gf += bf + xin * wf;
            gg += bg + xin * wg;
            go += bo + xin * wo;

            const float cprev = c_prev[(size_t)b * HID + j];
            const float cn = sigf(gf) * cprev + sigf(gi) * tanhf(gg);
            const float hn = sigf(go) * tanhf(cn);
            c_next[(size_t)b * HID + j] = cn;
            h_next[(size_t)b * HID + j] = hn;
        }
    }
}

// pred[b] = dot(h[b,:], W_lin) + b_lin ; writes out[b, t] and feedback buffer
__global__ void pred_kernel(const float* __restrict__ h,
                            const float* __restrict__ W_lin,
                            const float* __restrict__ b_lin,
                            float* __restrict__ out,
                            float* __restrict__ xfb,
                            int t)
{
    const int b = blockIdx.x;
    const int tid = threadIdx.x;
    float s = 0.0f;
    for (int k = tid; k < HID; k += 256)
        s += h[(size_t)b * HID + k] * W_lin[k];

    // warp reduce
    #pragma unroll
    for (int off = 16; off > 0; off >>= 1)
        s += __shfl_xor_sync(0xFFFFFFFFu, s, off);

    __shared__ float red[8];
    if ((tid & 31) == 0) red[tid >> 5] = s;
    __syncthreads();
    if (tid == 0) {
        float tot = 0.0f;
        #pragma unroll
        for (int w = 0; w < 8; ++w) tot += red[w];
        const float v = tot + b_lin[0];
        out[(size_t)b * TTOT + t] = v;
        xfb[b] = v;
    }
}

extern "C" void kernel_launch(void* const* d_in, const int* in_sizes, int n_in,
                              void* d_out, int out_size) {
    const float* x     = (const float*)d_in[0];  // [256, 80]
    const float* W_ih  = (const float*)d_in[1];  // [8192, 1]
    const float* W_hh  = (const float*)d_in[2];  // [8192, 2048]
    const float* b_ih  = (const float*)d_in[3];  // [8192]
    const float* b_hh  = (const float*)d_in[4];  // [8192]
    const float* W_lin = (const float*)d_in[5];  // [1, 2048]
    const float* b_lin = (const float*)d_in[6];  // [1]
    float* out = (float*)d_out;                  // [256, 160]

    float *hbuf, *cbuf, *xfb;
    cudaGetSymbolAddress((void**)&hbuf, g_h);
    cudaGetSymbolAddress((void**)&cbuf, g_c);
    cudaGetSymbolAddress((void**)&xfb,  g_xfb);

    // zero initial state (buffer 0)
    {
        int n = BH;
        int threads = 512;
        int blocks = (n + threads - 1) / threads;
        init_zero_kernel<<<blocks, threads>>>(hbuf, cbuf, n);
    }

    dim3 grid(BATCH / BM, HID / 32);

    for (int t = 0; t < TTOT; ++t) {
        const int cur = t & 1;
        const float* xvec;
        int xstride;
        if (t < TOBS) { xvec = x + t; xstride = TOBS; }
        else          { xvec = xfb;  xstride = 1; }

        lstm_step_kernel<<<grid, NTHREADS>>>(
            hbuf + (size_t)cur * BH, cbuf + (size_t)cur * BH,
            hbuf + (size_t)(1 - cur) * BH, cbuf + (size_t)(1 - cur) * BH,
            W_hh, W_ih, b_ih, b_hh, xvec, xstride);

        pred_kernel<<<BATCH, 256>>>(
            hbuf + (size_t)(1 - cur) * BH, W_lin, b_lin, out, xfb, t);
    }
}

// round 4
// speedup vs baseline: 2.4165x; 2.4165x over previous
#include <cuda_runtime.h>
#include <cuda_bf16.h>
#include <cstdint>

#define BATCH 256
#define TOBS  80
#define TTOT  160
#define HID   2048
#define HID4  8192
#define BH    (BATCH * HID)

#define NT      256
#define BK      64                   // K elements per chunk (bf16) = 128 bytes/row
#define NCH     96                   // 3 * (2048/64) concatenated-K chunks
#define NSTAGE  4
#define TILE_B  (128 * 128)          // 16 KB (128 rows x 128 bytes)
#define STAGE_B (2 * TILE_B)         // A tile + B tile
#define CTRL_B  2048
#define SMEM_DYN (1024 + CTRL_B + NSTAGE * STAGE_B)

// ---------------- persistent device state ----------------
__device__ float          g_c[BH];
__device__ __nv_bfloat16  g_hhi[2 * BH];
__device__ __nv_bfloat16  g_hlo[2 * BH];
__device__ __nv_bfloat16  g_whi[(size_t)HID4 * HID];   // gate-interleaved W_hh hi
__device__ __nv_bfloat16  g_wlo[(size_t)HID4 * HID];   // gate-interleaved W_hh lo

// ---------------- helpers ----------------
static __device__ __forceinline__ uint32_t smem_u32(const void* p) {
    uint32_t a;
    asm("{ .reg .u64 t; cvta.to.shared.u64 t, %1; cvt.u32.u64 %0, t; }" : "=r"(a) : "l"(p));
    return a;
}
static __device__ __forceinline__ void cpa16(uint32_t dst, const void* src) {
    asm volatile("cp.async.cg.shared.global [%0], [%1], 16;" :: "r"(dst), "l"(src) : "memory");
}
static __device__ __forceinline__ void cpa_commit() {
    asm volatile("cp.async.commit_group;" ::: "memory");
}
template <int N>
static __device__ __forceinline__ void cpa_wait() {
    asm volatile("cp.async.wait_group %0;" :: "n"(N) : "memory");
}
static __device__ __forceinline__ void ldsm4(uint32_t* r, uint32_t a) {
    asm volatile("ldmatrix.sync.aligned.m8n8.x4.shared.b16 {%0,%1,%2,%3}, [%4];"
                 : "=r"(r[0]), "=r"(r[1]), "=r"(r[2]), "=r"(r[3]) : "r"(a));
}
static __device__ __forceinline__ void mma16816(float* d, const uint32_t* a, const uint32_t* b) {
    asm volatile("mma.sync.aligned.m16n8k16.row.col.f32.bf16.bf16.f32 "
                 "{%0,%1,%2,%3}, {%4,%5,%6,%7}, {%8,%9}, {%0,%1,%2,%3};"
                 : "+f"(d[0]), "+f"(d[1]), "+f"(d[2]), "+f"(d[3])
                 : "r"(a[0]), "r"(a[1]), "r"(a[2]), "r"(a[3]), "r"(b[0]), "r"(b[1]));
}
static __device__ __forceinline__ float sig_f(float x) {
    return __fdividef(1.0f, 1.0f + __expf(-x));
}
static __device__ __forceinline__ float tanh_f(float x) {
    return __fdividef(2.0f, 1.0f + __expf(-2.0f * x)) - 1.0f;
}

// Load one chunk (A tile 128xBK + B tile 128xBK) into a stage via cp.async, SW128.
static __device__ __forceinline__ void load_chunk(
    uint32_t st, const __nv_bfloat16* __restrict__ A, const __nv_bfloat16* __restrict__ B,
    int m0, int n0, int koff, int tid)
{
#pragma unroll
    for (int r = 0; r < 4; ++r) {
        int q   = tid + NT * r;             // 0..1023 16B chunks
        int row = q >> 3;
        int cb  = (q & 7) * 16;
        uint32_t sw = (uint32_t)(row * 128) + (uint32_t)(cb ^ ((row & 7) * 16));
        const char* ga = (const char*)(A + (size_t)(m0 + row) * HID + koff) + cb;
        const char* gb = (const char*)(B + (size_t)(n0 + row) * HID + koff) + cb;
        cpa16(st + sw, ga);
        cpa16(st + TILE_B + sw, gb);
    }
}

// ---------------- prep kernels ----------------
__global__ void wconv_kernel(const float* __restrict__ W,
                             __nv_bfloat16* __restrict__ whi,
                             __nv_bfloat16* __restrict__ wlo)
{
    int n = blockIdx.x;                  // gate-interleaved row: n = 4*j + g
    int j = n >> 2, g = n & 3;
    const float4* src = (const float4*)(W + ((size_t)g * HID + j) * HID);
    size_t dst = (size_t)n * HID;
#pragma unroll
    for (int r = 0; r < 2; ++r) {
        int q = threadIdx.x + 256 * r;   // 0..511 float4s
        float4 v = src[q];
        int k = q * 4;
        float xs[4] = {v.x, v.y, v.z, v.w};
#pragma unroll
        for (int c = 0; c < 4; ++c) {
            __nv_bfloat16 hi = __float2bfloat16(xs[c]);
            whi[dst + k + c] = hi;
            wlo[dst + k + c] = __float2bfloat16(xs[c] - __bfloat162float(hi));
        }
    }
}

__global__ void init_kernel(float* __restrict__ cbuf,
                            __nv_bfloat16* __restrict__ h0hi,
                            __nv_bfloat16* __restrict__ h0lo,
                            float* __restrict__ out,
                            const float* __restrict__ b_lin)
{
    int i = blockIdx.x * blockDim.x + threadIdx.x;
    if (i < BH) {
        cbuf[i] = 0.0f;
        h0hi[i] = __float2bfloat16(0.0f);
        h0lo[i] = __float2bfloat16(0.0f);
    }
    if (i < BATCH * TTOT) out[i] = b_lin[0];
}

// ---------------- fused LSTM step: bf16x3 GEMM (mma.sync) + cell + pred ----------------
__global__ void __launch_bounds__(NT, 1)
lstm_step(const __nv_bfloat16* __restrict__ Ahi, const __nv_bfloat16* __restrict__ Alo,
          __nv_bfloat16* __restrict__ Ahi_n, __nv_bfloat16* __restrict__ Alo_n,
          float* __restrict__ cbuf,
          const __nv_bfloat16* __restrict__ Whi, const __nv_bfloat16* __restrict__ Wlo,
          const float* __restrict__ W_ih, const float* __restrict__ b_ih,
          const float* __restrict__ b_hh, const float* __restrict__ W_lin,
          float* __restrict__ out,
          const float* __restrict__ xvec, int xstride, int t)
{
    extern __shared__ char smem_raw[];
    const int tid  = threadIdx.x;
    const int wid  = tid >> 5;
    const int lane = tid & 31;
    const int warp_m = wid & 1;          // 2 x 64 rows
    const int warp_n = wid >> 1;         // 4 x 32 cols
    const int m0 = blockIdx.x * 128;
    const int n0 = blockIdx.y * 128;     // gate-interleaved col base
    const int j0 = n0 >> 2;

    uint32_t sb    = smem_u32(smem_raw);
    uint32_t sbase = (sb + 1023) & ~1023u;
    char*    ctrl  = smem_raw + (sbase - sb);
    uint32_t tiles = sbase + CTRL_B;
    float* bias_s = (float*)(ctrl + 0);      // 128
    float* wih_s  = (float*)(ctrl + 512);    // 128
    float* rowsum = (float*)(ctrl + 1024);   // 128
    float* wlin_s = (float*)(ctrl + 1536);   // 32

    if (tid < 128) {
        int j = j0 + (tid >> 2);
        int g = tid & 3;
        bias_s[tid] = b_ih[g * HID + j] + b_hh[g * HID + j];
        wih_s[tid]  = W_ih[g * HID + j];
        rowsum[tid] = 0.0f;
    }
    if (tid < 32) wlin_s[tid] = W_lin[j0 + tid];
    __syncthreads();

    float acc[4][4][4];
#pragma unroll
    for (int i = 0; i < 4; ++i)
#pragma unroll
        for (int jf = 0; jf < 4; ++jf)
#pragma unroll
            for (int kf = 0; kf < 4; ++kf) acc[i][jf][kf] = 0.0f;

    // ldmatrix lane-address components (SW128: xor mask = (row&7)*16, row-invariant per lane)
    const int xm = (lane & 7) * 16;
    int arow[4], brow[2];
#pragma unroll
    for (int mf = 0; mf < 4; ++mf)
        arow[mf] = (warp_m * 64 + mf * 16 + (lane & 15)) * 128;
#pragma unroll
    for (int q = 0; q < 2; ++q)
        brow[q] = TILE_B + (warp_n * 32 + (lane & 7) + ((lane & 16) ? 8 : 0) + q * 16) * 128;
    const int acoladd = (lane & 16) ? 16 : 0;
    const int bcoladd = (lane & 8) ? 16 : 0;

    // Prologue: chunks 0..NSTAGE-2
#pragma unroll
    for (int pc = 0; pc < NSTAGE - 1; ++pc) {
        load_chunk(tiles + pc * STAGE_B, Ahi, Whi, m0, n0, pc * BK, tid);
        cpa_commit();
    }

    for (int c = 0; c < NCH; ++c) {
        cpa_wait<NSTAGE - 2>();
        __syncthreads();

        // refill oldest-consumed stage with chunk c+NSTAGE-1
        {
            int cn = c + NSTAGE - 1;
            if (cn < NCH) {
                const __nv_bfloat16* As = (cn < 64) ? Ahi : Alo;
                const __nv_bfloat16* Bs = (cn >= 32 && cn < 64) ? Wlo : Whi;
                load_chunk(tiles + (cn & (NSTAGE - 1)) * STAGE_B, As, Bs,
                           m0, n0, (cn & 31) * BK, tid);
            }
            cpa_commit();
        }

        // compute from stage c%NSTAGE
        uint32_t st = tiles + (c & (NSTAGE - 1)) * STAGE_B;
#pragma unroll
        for (int kk = 0; kk < 4; ++kk) {           // 4 x k16
            uint32_t a[4][4], b[2][4];
            int colA = kk * 32 + acoladd;
            int colB = kk * 32 + bcoladd;
#pragma unroll
            for (int mf = 0; mf < 4; ++mf)
                ldsm4(a[mf], st + arow[mf] + (uint32_t)(colA ^ xm));
#pragma unroll
            for (int q = 0; q < 2; ++q)
                ldsm4(b[q], st + brow[q] + (uint32_t)(colB ^ xm));
#pragma unroll
            for (int mf = 0; mf < 4; ++mf) {
#pragma unroll
                for (int nf = 0; nf < 4; ++nf) {
                    const uint32_t bp[2] = { b[nf >> 1][(nf & 1) * 2],
                                             b[nf >> 1][(nf & 1) * 2 + 1] };
                    mma16816(acc[mf][nf], a[mf], bp);
                }
            }
        }
    }

    // ---- epilogue: gate exchange + LSTM cell + prediction ----
    const bool oddl = (lane & 1);
    const int slot  = (lane >> 1) & 1;
    const int rloc0 = warp_m * 64 + (lane >> 2) + (oddl ? 8 : 0);

#pragma unroll
    for (int mf = 0; mf < 4; ++mf) {
        const int rloc = rloc0 + mf * 16;
        const int m = m0 + rloc;
        const float xin = xvec[(size_t)m * xstride];
        float predp = 0.0f;
#pragma unroll
        for (int nf = 0; nf < 4; ++nf) {
            float c0 = acc[mf][nf][0], c1 = acc[mf][nf][1];
            float c2 = acc[mf][nf][2], c3 = acc[mf][nf][3];
            float t0 = __shfl_xor_sync(0xffffffffu, c0, 1);
            float t1 = __shfl_xor_sync(0xffffffffu, c1, 1);
            float t2 = __shfl_xor_sync(0xffffffffu, c2, 1);
            float t3 = __shfl_xor_sync(0xffffffffu, c3, 1);
            float gi, gf, gg, go;
            if (!oddl) { gi = c0; gf = c1; gg = t0; go = t1; }
            else       { gi = t2; gf = t3; gg = c2; go = c3; }

            const int jl = warp_n * 8 + nf * 2 + slot;
            const int nb = jl * 4;
            gi += bias_s[nb + 0] + xin * wih_s[nb + 0];
            gf += bias_s[nb + 1] + xin * wih_s[nb + 1];
            gg += bias_s[nb + 2] + xin * wih_s[nb + 2];
            go += bias_s[nb + 3] + xin * wih_s[nb + 3];

            const size_t off = (size_t)m * HID + (j0 + jl);
            float cp = cbuf[off];
            float cn = sig_f(gf) * cp + sig_f(gi) * tanh_f(gg);
            cbuf[off] = cn;
            float hn = sig_f(go) * tanh_f(cn);

            __nv_bfloat16 hi = __float2bfloat16(hn);
            Ahi_n[off] = hi;
            Alo_n[off] = __float2bfloat16(hn - __bfloat162float(hi));
            predp += hn * wlin_s[jl];
        }
        atomicAdd(&rowsum[rloc], predp);
    }
    __syncthreads();
    if (tid < 128)
        atomicAdd(&out[(size_t)(m0 + tid) * TTOT + t], rowsum[tid]);
}

// ---------------- host launch ----------------
extern "C" void kernel_launch(void* const* d_in, const int* in_sizes, int n_in,
                              void* d_out, int out_size) {
    const float* x     = (const float*)d_in[0];
    const float* W_ih  = (const float*)d_in[1];
    const float* W_hh  = (const float*)d_in[2];
    const float* b_ih  = (const float*)d_in[3];
    const float* b_hh  = (const float*)d_in[4];
    const float* W_lin = (const float*)d_in[5];
    const float* b_lin = (const float*)d_in[6];
    float* out = (float*)d_out;

    float *cbuf;
    __nv_bfloat16 *hhi, *hlo, *whi, *wlo;
    cudaGetSymbolAddress((void**)&cbuf, g_c);
    cudaGetSymbolAddress((void**)&hhi,  g_hhi);
    cudaGetSymbolAddress((void**)&hlo,  g_hlo);
    cudaGetSymbolAddress((void**)&whi,  g_whi);
    cudaGetSymbolAddress((void**)&wlo,  g_wlo);

    cudaFuncSetAttribute(lstm_step, cudaFuncAttributeMaxDynamicSharedMemorySize, SMEM_DYN);

    wconv_kernel<<<HID4, 256>>>(W_hh, whi, wlo);
    init_kernel<<<(BH + 255) / 256, 256>>>(cbuf, hhi, hlo, out, b_lin);

    dim3 grid(BATCH / 128, HID4 / 128);

    for (int t = 0; t < TTOT; ++t) {
        const int cur = t & 1;
        const float* xvec;
        int xstride;
        if (t < TOBS) { xvec = x + t;         xstride = TOBS; }
        else          { xvec = out + (t - 1); xstride = TTOT; }

        lstm_step<<<grid, NT, SMEM_DYN>>>(
            hhi + (size_t)cur * BH, hlo + (size_t)cur * BH,
            hhi + (size_t)(1 - cur) * BH, hlo + (size_t)(1 - cur) * BH,
            cbuf, whi, wlo,
            W_ih, b_ih, b_hh, W_lin,
            out, xvec, xstride, t);
    }
}

// round 6
// speedup vs baseline: 2.7094x; 1.1212x over previous
#include <cuda_runtime.h>
#include <cuda_bf16.h>
#include <cstdint>

#define BATCH 256
#define TOBS  80
#define TTOT  160
#define HID   2048
#define HID4  8192
#define BH    (BATCH * HID)

#define NT      256
#define BM      64                   // CTA rows (batch)
#define BN      128                  // CTA cols (gate-interleaved)
#define BK      64                   // K per chunk (bf16) = 128 bytes/row
#define NCH     96                   // 3 * (2048/64) concatenated-K chunks
#define NSTAGE  4
#define TILE_A  (BM * 128)           // 8 KB
#define TILE_BB (BN * 128)           // 16 KB
#define STAGE_B (TILE_A + TILE_BB)   // 24 KB
#define CTRL_B  2048
#define SMEM_DYN (1024 + CTRL_B + NSTAGE * STAGE_B)

// ---------------- persistent device state ----------------
__device__ float          g_c[BH];
__device__ __nv_bfloat16  g_hhi[2 * BH];
__device__ __nv_bfloat16  g_hlo[2 * BH];
__device__ __nv_bfloat16  g_whi[(size_t)HID4 * HID];   // gate-interleaved W_hh hi
__device__ __nv_bfloat16  g_wlo[(size_t)HID4 * HID];   // gate-interleaved W_hh lo

// ---------------- helpers ----------------
static __device__ __forceinline__ uint32_t smem_u32(const void* p) {
    uint32_t a;
    asm("{ .reg .u64 t; cvta.to.shared.u64 t, %1; cvt.u32.u64 %0, t; }" : "=r"(a) : "l"(p));
    return a;
}
static __device__ __forceinline__ void cpa16(uint32_t dst, const void* src) {
    asm volatile("cp.async.cg.shared.global [%0], [%1], 16;" :: "r"(dst), "l"(src) : "memory");
}
static __device__ __forceinline__ void cpa_commit() {
    asm volatile("cp.async.commit_group;" ::: "memory");
}
template <int N>
static __device__ __forceinline__ void cpa_wait() {
    asm volatile("cp.async.wait_group %0;" :: "n"(N) : "memory");
}
static __device__ __forceinline__ void ldsm4(uint32_t* r, uint32_t a) {
    asm volatile("ldmatrix.sync.aligned.m8n8.x4.shared.b16 {%0,%1,%2,%3}, [%4];"
                 : "=r"(r[0]), "=r"(r[1]), "=r"(r[2]), "=r"(r[3]) : "r"(a));
}
static __device__ __forceinline__ void mma16816(float* d, const uint32_t* a, const uint32_t* b) {
    asm volatile("mma.sync.aligned.m16n8k16.row.col.f32.bf16.bf16.f32 "
                 "{%0,%1,%2,%3}, {%4,%5,%6,%7}, {%8,%9}, {%0,%1,%2,%3};"
                 : "+f"(d[0]), "+f"(d[1]), "+f"(d[2]), "+f"(d[3])
                 : "r"(a[0]), "r"(a[1]), "r"(a[2]), "r"(a[3]), "r"(b[0]), "r"(b[1]));
}
static __device__ __forceinline__ float sig_f(float x) {
    return __fdividef(1.0f, 1.0f + __expf(-x));
}
static __device__ __forceinline__ float tanh_f(float x) {
    return __fdividef(2.0f, 1.0f + __expf(-2.0f * x)) - 1.0f;
}

// Load one chunk (A tile BMxBK + B tile BNxBK) into a stage via cp.async, SW128.
static __device__ __forceinline__ void load_chunk(
    uint32_t st, const __nv_bfloat16* __restrict__ A, const __nv_bfloat16* __restrict__ B,
    int m0, int n0, int koff, int tid)
{
    // A: 64 rows * 8 chunks = 512 16B units
#pragma unroll
    for (int r = 0; r < 2; ++r) {
        int q   = tid + NT * r;
        int row = q >> 3;
        int cb  = (q & 7) * 16;
        uint32_t sw = (uint32_t)(row * 128) + (uint32_t)(cb ^ ((row & 7) * 16));
        const char* ga = (const char*)(A + (size_t)(m0 + row) * HID + koff) + cb;
        cpa16(st + sw, ga);
    }
    // B: 128 rows * 8 chunks = 1024 16B units
#pragma unroll
    for (int r = 0; r < 4; ++r) {
        int q   = tid + NT * r;
        int row = q >> 3;
        int cb  = (q & 7) * 16;
        uint32_t sw = (uint32_t)(row * 128) + (uint32_t)(cb ^ ((row & 7) * 16));
        const char* gb = (const char*)(B + (size_t)(n0 + row) * HID + koff) + cb;
        cpa16(st + TILE_A + sw, gb);
    }
}

// ---------------- prep kernels ----------------
__global__ void wconv_kernel(const float* __restrict__ W,
                             __nv_bfloat16* __restrict__ whi,
                             __nv_bfloat16* __restrict__ wlo)
{
    int n = blockIdx.x;                  // gate-interleaved row: n = 4*j + g
    int j = n >> 2, g = n & 3;
    const float4* src = (const float4*)(W + ((size_t)g * HID + j) * HID);
    size_t dst = (size_t)n * HID;
#pragma unroll
    for (int r = 0; r < 2; ++r) {
        int q = threadIdx.x + 256 * r;   // 0..511 float4s
        float4 v = src[q];
        int k = q * 4;
        float xs[4] = {v.x, v.y, v.z, v.w};
#pragma unroll
        for (int c = 0; c < 4; ++c) {
            __nv_bfloat16 hi = __float2bfloat16(xs[c]);
            whi[dst + k + c] = hi;
            wlo[dst + k + c] = __float2bfloat16(xs[c] - __bfloat162float(hi));
        }
    }
}

__global__ void init_kernel(float* __restrict__ cbuf,
                            __nv_bfloat16* __restrict__ h0hi,
                            __nv_bfloat16* __restrict__ h0lo,
                            float* __restrict__ out,
                            const float* __restrict__ b_lin)
{
    int i = blockIdx.x * blockDim.x + threadIdx.x;
    if (i < BH) {
        cbuf[i] = 0.0f;
        h0hi[i] = __float2bfloat16(0.0f);
        h0lo[i] = __float2bfloat16(0.0f);
    }
    if (i < BATCH * TTOT) out[i] = b_lin[0];
}

// ---------------- fused LSTM step: bf16x3 GEMM (mma.sync) + cell + pred ----------------
__global__ void __launch_bounds__(NT, 2)
lstm_step(const __nv_bfloat16* __restrict__ Ahi, const __nv_bfloat16* __restrict__ Alo,
          __nv_bfloat16* __restrict__ Ahi_n, __nv_bfloat16* __restrict__ Alo_n,
          float* __restrict__ cbuf,
          const __nv_bfloat16* __restrict__ Whi, const __nv_bfloat16* __restrict__ Wlo,
          const float* __restrict__ W_ih, const float* __restrict__ b_ih,
          const float* __restrict__ b_hh, const float* __restrict__ W_lin,
          float* __restrict__ out,
          const float* __restrict__ xvec, int xstride, int t)
{
    extern __shared__ char smem_raw[];
    const int tid  = threadIdx.x;
    const int wid  = tid >> 5;
    const int lane = tid & 31;
    const int warp_m = wid & 1;          // 2 x 32 rows
    const int warp_n = wid >> 1;         // 4 x 32 cols
    const int m0 = blockIdx.x * BM;
    const int n0 = blockIdx.y * BN;      // gate-interleaved col base
    const int j0 = n0 >> 2;

    uint32_t sb    = smem_u32(smem_raw);
    uint32_t sbase = (sb + 1023) & ~1023u;
    char*    ctrl  = smem_raw + (sbase - sb);
    uint32_t tiles = sbase + CTRL_B;
    float* bias_s = (float*)(ctrl + 0);      // 128
    float* wih_s  = (float*)(ctrl + 512);    // 128
    float* rowsum = (float*)(ctrl + 1024);   // 64
    float* wlin_s = (float*)(ctrl + 1536);   // 32

    if (tid < 128) {
        int j = j0 + (tid >> 2);
        int g = tid & 3;
        bias_s[tid] = b_ih[g * HID + j] + b_hh[g * HID + j];
        wih_s[tid]  = W_ih[g * HID + j];
    }
    if (tid < 64) rowsum[tid] = 0.0f;
    if (tid < 32) wlin_s[tid] = W_lin[j0 + tid];
    __syncthreads();

    float acc[2][4][4];
#pragma unroll
    for (int i = 0; i < 2; ++i)
#pragma unroll
        for (int jf = 0; jf < 4; ++jf)
#pragma unroll
            for (int kf = 0; kf < 4; ++kf) acc[i][jf][kf] = 0.0f;

    // ldmatrix lane-address components (SW128: xor mask = (row&7)*16, row-invariant per lane)
    const int xm = (lane & 7) * 16;
    int arow[2], brow[2];
#pragma unroll
    for (int mf = 0; mf < 2; ++mf)
        arow[mf] = (warp_m * 32 + mf * 16 + (lane & 15)) * 128;
#pragma unroll
    for (int q = 0; q < 2; ++q)
        brow[q] = TILE_A + (warp_n * 32 + (lane & 7) + ((lane & 16) ? 8 : 0) + q * 16) * 128;
    const int acoladd = (lane & 16) ? 16 : 0;
    const int bcoladd = (lane & 8) ? 16 : 0;

    // Prologue: chunks 0..NSTAGE-2
#pragma unroll
    for (int pc = 0; pc < NSTAGE - 1; ++pc) {
        load_chunk(tiles + pc * STAGE_B, Ahi, Whi, m0, n0, pc * BK, tid);
        cpa_commit();
    }

    for (int c = 0; c < NCH; ++c) {
        cpa_wait<NSTAGE - 2>();
        __syncthreads();

        // refill oldest-consumed stage with chunk c+NSTAGE-1
        {
            int cn = c + NSTAGE - 1;
            if (cn < NCH) {
                const __nv_bfloat16* As = (cn < 64) ? Ahi : Alo;
                const __nv_bfloat16* Bs = (cn >= 32 && cn < 64) ? Wlo : Whi;
                load_chunk(tiles + (cn & (NSTAGE - 1)) * STAGE_B, As, Bs,
                           m0, n0, (cn & 31) * BK, tid);
            }
            cpa_commit();
        }

        // compute from stage c%NSTAGE
        uint32_t st = tiles + (c & (NSTAGE - 1)) * STAGE_B;
#pragma unroll
        for (int kk = 0; kk < 4; ++kk) {           // 4 x k16
            uint32_t a[2][4], b[2][4];
            int colA = kk * 32 + acoladd;
            int colB = kk * 32 + bcoladd;
#pragma unroll
            for (int mf = 0; mf < 2; ++mf)
                ldsm4(a[mf], st + arow[mf] + (uint32_t)(colA ^ xm));
#pragma unroll
            for (int q = 0; q < 2; ++q)
                ldsm4(b[q], st + brow[q] + (uint32_t)(colB ^ xm));
#pragma unroll
            for (int mf = 0; mf < 2; ++mf) {
#pragma unroll
                for (int nf = 0; nf < 4; ++nf) {
                    const uint32_t bp[2] = { b[nf >> 1][(nf & 1) * 2],
                                             b[nf >> 1][(nf & 1) * 2 + 1] };
                    mma16816(acc[mf][nf], a[mf], bp);
                }
            }
        }
    }

    // ---- epilogue: gate exchange + LSTM cell + prediction ----
    const bool oddl = (lane & 1);
    const int slot  = (lane >> 1) & 1;
    const int rloc0 = warp_m * 32 + (lane >> 2) + (oddl ? 8 : 0);

#pragma unroll
    for (int mf = 0; mf < 2; ++mf) {
        const int rloc = rloc0 + mf * 16;
        const int m = m0 + rloc;
        const float xin = xvec[(size_t)m * xstride];
        float predp = 0.0f;
#pragma unroll
        for (int nf = 0; nf < 4; ++nf) {
            float c0 = acc[mf][nf][0], c1 = acc[mf][nf][1];
            float c2 = acc[mf][nf][2], c3 = acc[mf][nf][3];
            float t0 = __shfl_xor_sync(0xffffffffu, c0, 1);
            float t1 = __shfl_xor_sync(0xffffffffu, c1, 1);
            float t2 = __shfl_xor_sync(0xffffffffu, c2, 1);
            float t3 = __shfl_xor_sync(0xffffffffu, c3, 1);
            float gi, gf, gg, go;
            if (!oddl) { gi = c0; gf = c1; gg = t0; go = t1; }
            else       { gi = t2; gf = t3; gg = c2; go = c3; }

            const int jl = warp_n * 8 + nf * 2 + slot;
            const int nb = jl * 4;
            gi += bias_s[nb + 0] + xin * wih_s[nb + 0];
            gf += bias_s[nb + 1] + xin * wih_s[nb + 1];
            gg += bias_s[nb + 2] + xin * wih_s[nb + 2];
            go += bias_s[nb + 3] + xin * wih_s[nb + 3];

            const size_t off = (size_t)m * HID + (j0 + jl);
            float cp = cbuf[off];
            float cn = sig_f(gf) * cp + sig_f(gi) * tanh_f(gg);
            cbuf[off] = cn;
            float hn = sig_f(go) * tanh_f(cn);

            __nv_bfloat16 hi = __float2bfloat16(hn);
            Ahi_n[off] = hi;
            Alo_n[off] = __float2bfloat16(hn - __bfloat162float(hi));
            predp += hn * wlin_s[jl];
        }
        atomicAdd(&rowsum[rloc], predp);
    }
    __syncthreads();
    if (tid < 64)
        atomicAdd(&out[(size_t)(m0 + tid) * TTOT + t], rowsum[tid]);
}

// ---------------- host launch ----------------
extern "C" void kernel_launch(void* const* d_in, const int* in_sizes, int n_in,
                              void* d_out, int out_size) {
    const float* x     = (const float*)d_in[0];
    const float* W_ih  = (const float*)d_in[1];
    const float* W_hh  = (const float*)d_in[2];
    const float* b_ih  = (const float*)d_in[3];
    const float* b_hh  = (const float*)d_in[4];
    const float* W_lin = (const float*)d_in[5];
    const float* b_lin = (const float*)d_in[6];
    float* out = (float*)d_out;

    float *cbuf;
    __nv_bfloat16 *hhi, *hlo, *whi, *wlo;
    cudaGetSymbolAddress((void**)&cbuf, g_c);
    cudaGetSymbolAddress((void**)&hhi,  g_hhi);
    cudaGetSymbolAddress((void**)&hlo,  g_hlo);
    cudaGetSymbolAddress((void**)&whi,  g_whi);
    cudaGetSymbolAddress((void**)&wlo,  g_wlo);

    cudaFuncSetAttribute(lstm_step, cudaFuncAttributeMaxDynamicSharedMemorySize, SMEM_DYN);

    wconv_kernel<<<HID4, 256>>>(W_hh, whi, wlo);
    init_kernel<<<(BH + 255) / 256, 256>>>(cbuf, hhi, hlo, out, b_lin);

    dim3 grid(BATCH / BM, HID4 / BN);

    for (int t = 0; t < TTOT; ++t) {
        const int cur = t & 1;
        const float* xvec;
        int xstride;
        if (t < TOBS) { xvec = x + t;         xstride = TOBS; }
        else          { xvec = out + (t - 1); xstride = TTOT; }

        lstm_step<<<grid, NT, SMEM_DYN>>>(
            hhi + (size_t)cur * BH, hlo + (size_t)cur * BH,
            hhi + (size_t)(1 - cur) * BH, hlo + (size_t)(1 - cur) * BH,
            cbuf, whi, wlo,
            W_ih, b_ih, b_hh, W_lin,
            out, xvec, xstride, t);
    }
}